// round 2
// baseline (speedup 1.0000x reference)
#include <cuda_runtime.h>

// MultiLayerGAT: 2-layer GAT, N=50000 nodes, E=800000 edges (+N self loops),
// IN_F=128, HEADS=4, HID=64 -> F_OUT=256 per layer, leaky_relu(0.2) attention,
// segment softmax by dst, relu between/after layers.
//
// NOTE: edge_index arrives as int32 (JAX x64 disabled -> jnp.int64 demotes).
//
// Pipeline per launch:
//   CSR build (deg init=1 for self loop, histogram, single-block scan, scatter)
//   layer l: GEMM h = X @ Wl ; per-node alpha_src/dst dots ; per-node
//            3-pass softmax-aggregate (max, sum, weighted gather) + bias + relu

#define N_NODES 50000
#define N_EDGES 800000
#define EP      (N_EDGES + N_NODES)   // 850000 edges incl. self loops
#define F_OUT   256                   // HEADS * HID
#define HID     64
#define NEG     0.2f

// ---------------- scratch (static device memory; no allocs) ----------------
__device__ float g_hfeat[(size_t)N_NODES * F_OUT];  // current layer h = X @ W
__device__ float g_x2[(size_t)N_NODES * F_OUT];     // layer-1 output / layer-2 input
__device__ float g_alpha[(size_t)N_NODES * 8];      // [n][0..3]=alpha_src, [4..7]=alpha_dst
__device__ int   g_deg[N_NODES];
__device__ int   g_off[N_NODES + 1];
__device__ int   g_cursor[N_NODES];
__device__ int   g_esrc[EP];                        // src node id, grouped by dst

// ---------------- CSR build ----------------
__global__ void k_init_deg() {
    int i = blockIdx.x * blockDim.x + threadIdx.x;
    if (i < N_NODES) g_deg[i] = 1;  // self loop
}

__global__ void k_hist(const int* __restrict__ ei) {
    int i = blockIdx.x * blockDim.x + threadIdx.x;
    if (i < N_EDGES) {
        int d = ei[N_EDGES + i];
        atomicAdd(&g_deg[d], 1);
    }
}

// single-block exclusive scan over g_deg -> g_off, also seeds g_cursor
__global__ void k_scan() {
    __shared__ int sdata[1024];
    __shared__ int s_run;
    int tid = threadIdx.x;
    if (tid == 0) s_run = 0;
    __syncthreads();
    for (int base = 0; base < N_NODES; base += 1024) {
        int i = base + tid;
        int v = (i < N_NODES) ? g_deg[i] : 0;
        sdata[tid] = v;
        __syncthreads();
        #pragma unroll
        for (int off = 1; off < 1024; off <<= 1) {
            int t = (tid >= off) ? sdata[tid - off] : 0;
            __syncthreads();
            sdata[tid] += t;
            __syncthreads();
        }
        int excl = sdata[tid] - v + s_run;
        if (i < N_NODES) { g_off[i] = excl; g_cursor[i] = excl; }
        __syncthreads();
        if (tid == 0) s_run += sdata[1023];
        __syncthreads();
    }
    if (tid == 0) g_off[N_NODES] = s_run;
}

__global__ void k_scatter(const int* __restrict__ ei) {
    int i = blockIdx.x * blockDim.x + threadIdx.x;
    if (i < N_EDGES) {
        int s = ei[i];
        int d = ei[N_EDGES + i];
        int pos = atomicAdd(&g_cursor[d], 1);
        g_esrc[pos] = s;
    } else if (i < EP) {
        int n = i - N_EDGES;
        int pos = atomicAdd(&g_cursor[n], 1);
        g_esrc[pos] = n;  // self loop
    }
}

// ---------------- GEMM: C[M x 256] = A[M x K] * B[K x 256] ----------------
#define BM 64
#define BN 64
#define BK 16
__global__ void k_gemm(const float* __restrict__ A, const float* __restrict__ B,
                       float* __restrict__ C, int M, int K) {
    __shared__ float As[BK][BM];
    __shared__ float Bs[BK][BN];
    int tid = threadIdx.x;
    int tx = tid & 15, ty = tid >> 4;
    int m0 = blockIdx.y * BM, n0 = blockIdx.x * BN;
    float acc[4][4] = {};
    for (int k0 = 0; k0 < K; k0 += BK) {
        #pragma unroll
        for (int i = 0; i < 4; i++) {
            int idx = tid + i * 256;          // 0..1023 over 64x16 A tile
            int r = idx >> 4, c = idx & 15;
            int gm = m0 + r;
            As[c][r] = (gm < M) ? A[(size_t)gm * K + k0 + c] : 0.f;
        }
        #pragma unroll
        for (int i = 0; i < 4; i++) {
            int idx = tid + i * 256;          // 16x64 B tile
            int r = idx >> 6, c = idx & 63;
            Bs[r][c] = B[(size_t)(k0 + r) * F_OUT + n0 + c];
        }
        __syncthreads();
        #pragma unroll
        for (int k = 0; k < BK; k++) {
            float a[4], b[4];
            #pragma unroll
            for (int i = 0; i < 4; i++) a[i] = As[k][ty * 4 + i];
            #pragma unroll
            for (int j = 0; j < 4; j++) b[j] = Bs[k][tx * 4 + j];
            #pragma unroll
            for (int i = 0; i < 4; i++)
                #pragma unroll
                for (int j = 0; j < 4; j++)
                    acc[i][j] = fmaf(a[i], b[j], acc[i][j]);
        }
        __syncthreads();
    }
    #pragma unroll
    for (int i = 0; i < 4; i++) {
        int gm = m0 + ty * 4 + i;
        if (gm < M) {
            #pragma unroll
            for (int j = 0; j < 4; j++)
                C[(size_t)gm * F_OUT + n0 + tx * 4 + j] = acc[i][j];
        }
    }
}

// ---------------- per-node attention dots ----------------
// alpha_src[n][h] = dot(h[n,h,:], a_src[h,:]) ; same for dst. One block per node.
__global__ void k_alpha(const float* __restrict__ h, const float* __restrict__ a_src,
                        const float* __restrict__ a_dst) {
    int n = blockIdx.x;
    int tid = threadIdx.x;
    int hh = tid >> 6, d = tid & 63;
    float hv = h[(size_t)n * F_OUT + tid];
    float vs = hv * a_src[hh * HID + d];
    float vd = hv * a_dst[hh * HID + d];
    #pragma unroll
    for (int o = 16; o > 0; o >>= 1) {
        vs += __shfl_down_sync(0xffffffffu, vs, o);
        vd += __shfl_down_sync(0xffffffffu, vd, o);
    }
    __shared__ float ps[8], pd[8];
    int wid = tid >> 5, lane = tid & 31;
    if (lane == 0) { ps[wid] = vs; pd[wid] = vd; }
    __syncthreads();
    if (tid < 4) {
        g_alpha[(size_t)n * 8 + tid]     = ps[2 * tid] + ps[2 * tid + 1];
        g_alpha[(size_t)n * 8 + 4 + tid] = pd[2 * tid] + pd[2 * tid + 1];
    }
}

// ---------------- per-node softmax + aggregate + bias + relu ----------------
// One block (256 threads = 256 output dims) per dst node. 3 passes over edges:
// max, exp-sum, weighted gather of h[src].
__global__ void k_agg(const float* __restrict__ h, const float* __restrict__ bias,
                      float* __restrict__ outp) {
    int n = blockIdx.x;
    int tid = threadIdx.x;
    int head = tid >> 6;
    int wid = tid >> 5, lane = tid & 31;
    int beg = g_off[n], end = g_off[n + 1];

    float ad[4];
    #pragma unroll
    for (int q = 0; q < 4; q++) ad[q] = g_alpha[(size_t)n * 8 + 4 + q];

    __shared__ float sred[8][4];
    __shared__ float bm[4], bd[4];

    // pass 1: per-head max of leaky(e)
    float m[4] = {-1e30f, -1e30f, -1e30f, -1e30f};
    for (int j = beg + tid; j < end; j += 256) {
        int s = g_esrc[j];
        #pragma unroll
        for (int q = 0; q < 4; q++) {
            float e = g_alpha[(size_t)s * 8 + q] + ad[q];
            e = (e > 0.f) ? e : NEG * e;
            m[q] = fmaxf(m[q], e);
        }
    }
    #pragma unroll
    for (int q = 0; q < 4; q++)
        #pragma unroll
        for (int o = 16; o > 0; o >>= 1)
            m[q] = fmaxf(m[q], __shfl_down_sync(0xffffffffu, m[q], o));
    if (lane == 0) {
        #pragma unroll
        for (int q = 0; q < 4; q++) sred[wid][q] = m[q];
    }
    __syncthreads();
    if (tid < 4) {
        float v = -1e30f;
        #pragma unroll
        for (int w = 0; w < 8; w++) v = fmaxf(v, sred[w][tid]);
        bm[tid] = v;
    }
    __syncthreads();
    float mm[4];
    #pragma unroll
    for (int q = 0; q < 4; q++) mm[q] = bm[q];

    // pass 2: per-head sum of exp(e - max)
    float sum[4] = {0.f, 0.f, 0.f, 0.f};
    for (int j = beg + tid; j < end; j += 256) {
        int s = g_esrc[j];
        #pragma unroll
        for (int q = 0; q < 4; q++) {
            float e = g_alpha[(size_t)s * 8 + q] + ad[q];
            e = (e > 0.f) ? e : NEG * e;
            sum[q] += __expf(e - mm[q]);
        }
    }
    #pragma unroll
    for (int q = 0; q < 4; q++)
        #pragma unroll
        for (int o = 16; o > 0; o >>= 1)
            sum[q] += __shfl_down_sync(0xffffffffu, sum[q], o);
    if (lane == 0) {
        #pragma unroll
        for (int q = 0; q < 4; q++) sred[wid][q] = sum[q];
    }
    __syncthreads();
    if (tid < 4) {
        float v = 0.f;
        #pragma unroll
        for (int w = 0; w < 8; w++) v += sred[w][tid];
        bd[tid] = v;
    }
    __syncthreads();
    float dn[4];
    #pragma unroll
    for (int q = 0; q < 4; q++) dn[q] = bd[q] + 1e-16f;

    // pass 3: weighted gather. Groups of 64 edges; 4 threads per edge compute
    // the 4 head weights into shared, then all 256 threads accumulate.
    __shared__ int   s_s[64];
    __shared__ float s_w[256];
    float acc = 0.f;
    for (int base = beg; base < end; base += 64) {
        int cnt = min(64, end - base);
        __syncthreads();
        int eidx = tid >> 2, hh = tid & 3;
        if (eidx < cnt) {
            int s = g_esrc[base + eidx];
            if (hh == 0) s_s[eidx] = s;
            float e = g_alpha[(size_t)s * 8 + hh] + ad[hh];
            e = (e > 0.f) ? e : NEG * e;
            s_w[tid] = __expf(e - mm[hh]) / dn[hh];   // tid == eidx*4+hh
        }
        __syncthreads();
        for (int k = 0; k < cnt; k++) {
            acc = fmaf(s_w[k * 4 + head], h[(size_t)s_s[k] * F_OUT + tid], acc);
        }
    }
    float o = acc + bias[tid];
    outp[(size_t)n * F_OUT + tid] = (o > 0.f) ? o : 0.f;
}

// ---------------- launch ----------------
extern "C" void kernel_launch(void* const* d_in, const int* in_sizes, int n_in,
                              void* d_out, int out_size) {
    const float* x      = (const float*)d_in[0];
    const int*   ei     = (const int*)d_in[1];     // int32! (JAX x64 disabled)
    const float* W1     = (const float*)d_in[2];
    const float* a_src1 = (const float*)d_in[3];
    const float* a_dst1 = (const float*)d_in[4];
    const float* b1     = (const float*)d_in[5];
    const float* W2     = (const float*)d_in[6];
    const float* a_src2 = (const float*)d_in[7];
    const float* a_dst2 = (const float*)d_in[8];
    const float* b2     = (const float*)d_in[9];
    float* out = (float*)d_out;

    float* hfeat; cudaGetSymbolAddress((void**)&hfeat, g_hfeat);
    float* x2;    cudaGetSymbolAddress((void**)&x2, g_x2);

    // CSR build (edges identical for both layers)
    k_init_deg<<<(N_NODES + 255) / 256, 256>>>();
    k_hist<<<(N_EDGES + 255) / 256, 256>>>(ei);
    k_scan<<<1, 1024>>>();
    k_scatter<<<(EP + 255) / 256, 256>>>(ei);

    dim3 ggrid(F_OUT / BN, (N_NODES + BM - 1) / BM);

    // layer 1
    k_gemm<<<ggrid, 256>>>(x, W1, hfeat, N_NODES, 128);
    k_alpha<<<N_NODES, 256>>>(hfeat, a_src1, a_dst1);
    k_agg<<<N_NODES, 256>>>(hfeat, b1, x2);

    // layer 2
    k_gemm<<<ggrid, 256>>>(x2, W2, hfeat, N_NODES, 256);
    k_alpha<<<N_NODES, 256>>>(hfeat, a_src2, a_dst2);
    k_agg<<<N_NODES, 256>>>(hfeat, b2, out);
}

// round 3
// speedup vs baseline: 1.2700x; 1.2700x over previous
#include <cuda_runtime.h>

// MultiLayerGAT: 2-layer GAT, N=50000 nodes, E=800000 edges (+N self loops),
// IN_F=128, HEADS=4, HID=64 -> F_OUT=256, leaky_relu(0.2) attention,
// segment softmax by dst, relu between/after layers.
// edge_index arrives as int32 (JAX x64 disabled).

#define N_NODES 50000
#define N_EDGES 800000
#define EP      (N_EDGES + N_NODES)   // 850000 edges incl. self loops
#define F_OUT   256                   // HEADS * HID
#define HID     64
#define NEG     0.2f
#define NBLK_SCAN ((N_NODES + 255) / 256)   // 196

// ---------------- scratch (static device memory; no allocs) ----------------
__device__ float g_hfeat[(size_t)N_NODES * F_OUT];
__device__ float g_x2[(size_t)N_NODES * F_OUT];
__device__ float g_alpha[(size_t)N_NODES * 8];   // [n][0..3]=src, [4..7]=dst
__device__ int   g_deg[N_NODES];
__device__ int   g_off[N_NODES + 1];
__device__ int   g_cursor[N_NODES];
__device__ int   g_bsum[NBLK_SCAN];
__device__ int   g_esrc[EP];                     // src ids grouped by dst

// ---------------- CSR build ----------------
__global__ void k_init_deg() {
    int i = blockIdx.x * blockDim.x + threadIdx.x;
    if (i < N_NODES) g_deg[i] = 1;  // self loop
}

__global__ void k_hist(const int* __restrict__ ei) {
    int i = blockIdx.x * blockDim.x + threadIdx.x;
    if (i < N_EDGES) atomicAdd(&g_deg[ei[N_EDGES + i]], 1);
}

// hierarchical exclusive scan: block partial inclusive scans -> top scan -> add
__global__ void k_scan_blk() {
    __shared__ int s[256];
    int i = blockIdx.x * 256 + threadIdx.x;
    int v = (i < N_NODES) ? g_deg[i] : 0;
    s[threadIdx.x] = v;
    __syncthreads();
    #pragma unroll
    for (int off = 1; off < 256; off <<= 1) {
        int t = (threadIdx.x >= off) ? s[threadIdx.x - off] : 0;
        __syncthreads();
        s[threadIdx.x] += t;
        __syncthreads();
    }
    if (i < N_NODES) g_off[i] = s[threadIdx.x];   // inclusive, local
    if (threadIdx.x == 255) g_bsum[blockIdx.x] = s[255];
}

__global__ void k_scan_top() {
    __shared__ int s[256];
    int t = threadIdx.x;
    int v = (t < NBLK_SCAN) ? g_bsum[t] : 0;
    s[t] = v;
    __syncthreads();
    #pragma unroll
    for (int off = 1; off < 256; off <<= 1) {
        int u = (t >= off) ? s[t - off] : 0;
        __syncthreads();
        s[t] += u;
        __syncthreads();
    }
    if (t < NBLK_SCAN) g_bsum[t] = s[t] - v;      // exclusive block offsets
}

__global__ void k_scan_add() {
    int i = blockIdx.x * 256 + threadIdx.x;
    if (i < N_NODES) {
        int excl = g_off[i] - g_deg[i] + g_bsum[blockIdx.x];
        g_off[i] = excl;
        g_cursor[i] = excl;
    }
    if (i == 0) g_off[N_NODES] = EP;   // total is static
}

__global__ void k_scatter(const int* __restrict__ ei) {
    int i = blockIdx.x * blockDim.x + threadIdx.x;
    if (i < N_EDGES) {
        int s = ei[i];
        int d = ei[N_EDGES + i];
        int pos = atomicAdd(&g_cursor[d], 1);
        g_esrc[pos] = s;
    } else if (i < EP) {
        int n = i - N_EDGES;
        int pos = atomicAdd(&g_cursor[n], 1);
        g_esrc[pos] = n;  // self loop
    }
}

// ---------------- GEMM: C[M x 256] = A[M x K] * B[K x 256] ----------------
// 128x128 tile, BK=16, 256 threads, 8x8 accumulators per thread.
#define GBM 128
#define GBN 128
#define GBK 16
__global__ __launch_bounds__(256) void k_gemm(const float* __restrict__ A,
                                              const float* __restrict__ B,
                                              float* __restrict__ C,
                                              int M, int K) {
    __shared__ float As[GBK][GBM + 4];
    __shared__ float Bs[GBK][GBN + 4];
    int tid = threadIdx.x;
    int tx = tid & 15, ty = tid >> 4;
    int m0 = blockIdx.y * GBM, n0 = blockIdx.x * GBN;
    float acc[8][8] = {};

    for (int k0 = 0; k0 < K; k0 += GBK) {
        // A tile: 128 rows x 16 cols, float4 loads along K
        #pragma unroll
        for (int i = 0; i < 2; i++) {
            int idx = tid + i * 256;          // 0..511 float4 slots
            int r = idx >> 2, c4 = (idx & 3) * 4;
            int gm = m0 + r;
            float4 v = make_float4(0.f, 0.f, 0.f, 0.f);
            if (gm < M) v = *(const float4*)&A[(size_t)gm * K + k0 + c4];
            As[c4 + 0][r] = v.x;
            As[c4 + 1][r] = v.y;
            As[c4 + 2][r] = v.z;
            As[c4 + 3][r] = v.w;
        }
        // B tile: 16 rows x 128 cols
        #pragma unroll
        for (int i = 0; i < 2; i++) {
            int idx = tid + i * 256;
            int r = idx >> 5, c = (idx & 31) * 4;
            *(float4*)&Bs[r][c] = *(const float4*)&B[(size_t)(k0 + r) * F_OUT + n0 + c];
        }
        __syncthreads();
        #pragma unroll
        for (int k = 0; k < GBK; k++) {
            float a[8], b[8];
            #pragma unroll
            for (int i = 0; i < 8; i++) a[i] = As[k][ty * 8 + i];
            #pragma unroll
            for (int j = 0; j < 8; j++) b[j] = Bs[k][tx * 8 + j];
            #pragma unroll
            for (int i = 0; i < 8; i++)
                #pragma unroll
                for (int j = 0; j < 8; j++)
                    acc[i][j] = fmaf(a[i], b[j], acc[i][j]);
        }
        __syncthreads();
    }
    #pragma unroll
    for (int i = 0; i < 8; i++) {
        int gm = m0 + ty * 8 + i;
        if (gm < M) {
            #pragma unroll
            for (int j = 0; j < 8; j += 4) {
                float4 v = make_float4(acc[i][j], acc[i][j + 1], acc[i][j + 2], acc[i][j + 3]);
                *(float4*)&C[(size_t)gm * F_OUT + n0 + tx * 8 + j] = v;
            }
        }
    }
}

// ---------------- per-node attention dots ----------------
__global__ void k_alpha(const float* __restrict__ h, const float* __restrict__ a_src,
                        const float* __restrict__ a_dst) {
    int n = blockIdx.x;
    int tid = threadIdx.x;
    int hh = tid >> 6, d = tid & 63;
    float hv = h[(size_t)n * F_OUT + tid];
    float vs = hv * a_src[hh * HID + d];
    float vd = hv * a_dst[hh * HID + d];
    #pragma unroll
    for (int o = 16; o > 0; o >>= 1) {
        vs += __shfl_down_sync(0xffffffffu, vs, o);
        vd += __shfl_down_sync(0xffffffffu, vd, o);
    }
    __shared__ float ps[8], pd[8];
    int wid = tid >> 5, lane = tid & 31;
    if (lane == 0) { ps[wid] = vs; pd[wid] = vd; }
    __syncthreads();
    if (tid < 4) {
        g_alpha[(size_t)n * 8 + tid]     = ps[2 * tid] + ps[2 * tid + 1];
        g_alpha[(size_t)n * 8 + 4 + tid] = pd[2 * tid] + pd[2 * tid + 1];
    }
}

// ---------------- per-node softmax + aggregate + bias + relu ----------------
__global__ void k_agg(const float* __restrict__ h, const float* __restrict__ bias,
                      float* __restrict__ outp) {
    int n = blockIdx.x;
    int tid = threadIdx.x;
    int head = tid >> 6;
    int wid = tid >> 5, lane = tid & 31;
    int beg = g_off[n], end = g_off[n + 1];

    float ad[4];
    #pragma unroll
    for (int q = 0; q < 4; q++) ad[q] = g_alpha[(size_t)n * 8 + 4 + q];

    __shared__ float sred[8][4];
    __shared__ float bm[4], bd[4];

    // pass 1: per-head max of leaky(e)
    float m[4] = {-1e30f, -1e30f, -1e30f, -1e30f};
    for (int j = beg + tid; j < end; j += 256) {
        int s = g_esrc[j];
        #pragma unroll
        for (int q = 0; q < 4; q++) {
            float e = g_alpha[(size_t)s * 8 + q] + ad[q];
            e = (e > 0.f) ? e : NEG * e;
            m[q] = fmaxf(m[q], e);
        }
    }
    #pragma unroll
    for (int q = 0; q < 4; q++)
        #pragma unroll
        for (int o = 16; o > 0; o >>= 1)
            m[q] = fmaxf(m[q], __shfl_down_sync(0xffffffffu, m[q], o));
    if (lane == 0) {
        #pragma unroll
        for (int q = 0; q < 4; q++) sred[wid][q] = m[q];
    }
    __syncthreads();
    if (tid < 4) {
        float v = -1e30f;
        #pragma unroll
        for (int w = 0; w < 8; w++) v = fmaxf(v, sred[w][tid]);
        bm[tid] = v;
    }
    __syncthreads();
    float mm[4];
    #pragma unroll
    for (int q = 0; q < 4; q++) mm[q] = bm[q];

    // pass 2: per-head sum of exp(e - max)
    float sum[4] = {0.f, 0.f, 0.f, 0.f};
    for (int j = beg + tid; j < end; j += 256) {
        int s = g_esrc[j];
        #pragma unroll
        for (int q = 0; q < 4; q++) {
            float e = g_alpha[(size_t)s * 8 + q] + ad[q];
            e = (e > 0.f) ? e : NEG * e;
            sum[q] += __expf(e - mm[q]);
        }
    }
    #pragma unroll
    for (int q = 0; q < 4; q++)
        #pragma unroll
        for (int o = 16; o > 0; o >>= 1)
            sum[q] += __shfl_down_sync(0xffffffffu, sum[q], o);
    if (lane == 0) {
        #pragma unroll
        for (int q = 0; q < 4; q++) sred[wid][q] = sum[q];
    }
    __syncthreads();
    if (tid < 4) {
        float v = 0.f;
        #pragma unroll
        for (int w = 0; w < 8; w++) v += sred[w][tid];
        bd[tid] = v;
    }
    __syncthreads();
    float dn[4];
    #pragma unroll
    for (int q = 0; q < 4; q++) dn[q] = bd[q] + 1e-16f;

    // pass 3: weighted gather, 64-edge chunks
    __shared__ int   s_s[64];
    __shared__ float s_w[256];
    float acc = 0.f;
    for (int base = beg; base < end; base += 64) {
        int cnt = min(64, end - base);
        __syncthreads();
        int eidx = tid >> 2, hh = tid & 3;
        if (eidx < cnt) {
            int s = g_esrc[base + eidx];
            if (hh == 0) s_s[eidx] = s;
            float e = g_alpha[(size_t)s * 8 + hh] + ad[hh];
            e = (e > 0.f) ? e : NEG * e;
            s_w[tid] = __expf(e - mm[hh]) / dn[hh];
        }
        __syncthreads();
        for (int k = 0; k < cnt; k++) {
            acc = fmaf(s_w[k * 4 + head], h[(size_t)s_s[k] * F_OUT + tid], acc);
        }
    }
    float o = acc + bias[tid];
    outp[(size_t)n * F_OUT + tid] = (o > 0.f) ? o : 0.f;
}

// ---------------- launch ----------------
extern "C" void kernel_launch(void* const* d_in, const int* in_sizes, int n_in,
                              void* d_out, int out_size) {
    const float* x      = (const float*)d_in[0];
    const int*   ei     = (const int*)d_in[1];     // int32
    const float* W1     = (const float*)d_in[2];
    const float* a_src1 = (const float*)d_in[3];
    const float* a_dst1 = (const float*)d_in[4];
    const float* b1     = (const float*)d_in[5];
    const float* W2     = (const float*)d_in[6];
    const float* a_src2 = (const float*)d_in[7];
    const float* a_dst2 = (const float*)d_in[8];
    const float* b2     = (const float*)d_in[9];
    float* out = (float*)d_out;

    float* hfeat; cudaGetSymbolAddress((void**)&hfeat, g_hfeat);
    float* x2;    cudaGetSymbolAddress((void**)&x2, g_x2);

    // CSR build
    k_init_deg<<<NBLK_SCAN, 256>>>();
    k_hist<<<(N_EDGES + 255) / 256, 256>>>(ei);
    k_scan_blk<<<NBLK_SCAN, 256>>>();
    k_scan_top<<<1, 256>>>();
    k_scan_add<<<NBLK_SCAN, 256>>>();
    k_scatter<<<(EP + 255) / 256, 256>>>(ei);

    dim3 ggrid(F_OUT / GBN, (N_NODES + GBM - 1) / GBM);

    // layer 1
    k_gemm<<<ggrid, 256>>>(x, W1, hfeat, N_NODES, 128);
    k_alpha<<<N_NODES, 256>>>(hfeat, a_src1, a_dst1);
    k_agg<<<N_NODES, 256>>>(hfeat, b1, x2);

    // layer 2
    k_gemm<<<ggrid, 256>>>(x2, W2, hfeat, N_NODES, 256);
    k_alpha<<<N_NODES, 256>>>(hfeat, a_src2, a_dst2);
    k_agg<<<N_NODES, 256>>>(hfeat, b2, out);
}